// round 14
// baseline (speedup 1.0000x reference)
#include <cuda_runtime.h>
#include <cuda_bf16.h>
#include <cstddef>

#define NPTS 10000
#define NB 16
#define BN_EPS 1e-5f
#define KSPLIT 5
#define NS_GRID 256

// ---------------- static device scratch (allocation-free) ----------------
__device__ float g_bufA[NB * 64 * NPTS];
__device__ float g_bufB[NB * 128 * NPTS];
__device__ float g_y5[NB * 256 * NPTS];
__device__ float g_stat[5 * 512];
__device__ float g_r[NB * 256];
__device__ float g_Spart[KSPLIT * NB * 256 * 256];
__device__ float g_nrm[NB];
__device__ float g_cov[NB * 256 * 256];
__device__ float g_part[16 * 256 * NB];
__device__ unsigned g_bar2[2];   // [0]=count, [1]=sense
// split-bf16 NS state planes
__device__ __nv_bfloat16 g_Yh[NB * 65536], g_Yl[NB * 65536];
__device__ __nv_bfloat16 g_Zh[NB * 65536], g_Zl[NB * 65536];
__device__ __nv_bfloat16 g_Ph[NB * 65536], g_Pl[NB * 65536];
__device__ __nv_bfloat16 g_Y2h[NB * 65536], g_Y2l[NB * 65536];
__device__ __nv_bfloat16 g_Z2h[NB * 65536], g_Z2l[NB * 65536];

// ---------------- tensor-core fragment primitives (validated R6/R10) ----------------
#define LDSM_X4(R, addr)                                                         \
    asm volatile("ldmatrix.sync.aligned.m8n8.x4.shared.b16 {%0,%1,%2,%3}, [%4];" \
                 : "=r"((R)[0]), "=r"((R)[1]), "=r"((R)[2]), "=r"((R)[3])        \
                 : "r"(addr))
#define LDSM_X4_T(R, addr)                                                             \
    asm volatile("ldmatrix.sync.aligned.m8n8.x4.trans.shared.b16 {%0,%1,%2,%3}, [%4];" \
                 : "=r"((R)[0]), "=r"((R)[1]), "=r"((R)[2]), "=r"((R)[3])              \
                 : "r"(addr))
#define MMA_BF16(C, A, B)                                                          \
    asm volatile(                                                                  \
        "mma.sync.aligned.m16n8k16.row.col.f32.bf16.bf16.f32 "                     \
        "{%0,%1,%2,%3},{%4,%5,%6,%7},{%8,%9},{%0,%1,%2,%3};"                       \
        : "+f"((C)[0]), "+f"((C)[1]), "+f"((C)[2]), "+f"((C)[3])                   \
        : "r"((A)[0]), "r"((A)[1]), "r"((A)[2]), "r"((A)[3]), "r"((B)[0]),         \
          "r"((B)[1]))

// ---------------- layer 0: 3 -> 64 raw, fused BN-stat accumulation ----------------
__global__ void k_layer0(const float* __restrict__ pts, const float* __restrict__ W0,
                         float* __restrict__ y, float* __restrict__ stat) {
    __shared__ float w[192];
    int t = threadIdx.x;
    if (t < 192) w[t] = W0[t];
    __syncthreads();
    int b = blockIdx.y;
    int n = blockIdx.x * 256 + t;
    bool valid = (n < NPTS);
    float p0 = 0.f, p1 = 0.f, p2 = 0.f;
    if (valid) {
        const float* p = pts + ((size_t)b * NPTS + n) * 3;
        p0 = p[0]; p1 = p[1]; p2 = p[2];
    }
    float* yo = y + (size_t)b * 64 * NPTS + n;
    int lane = t & 31;
#pragma unroll
    for (int o = 0; o < 64; ++o) {
        float v = w[o * 3] * p0 + w[o * 3 + 1] * p1 + w[o * 3 + 2] * p2;
        if (valid) yo[(size_t)o * NPTS] = v;
        float s = v, q = v * v;
#pragma unroll
        for (int m2 = 16; m2 >= 1; m2 >>= 1) {
            s += __shfl_xor_sync(0xffffffffu, s, m2);
            q += __shfl_xor_sync(0xffffffffu, q, m2);
        }
        if (lane == 0) { atomicAdd(&stat[o], s); atomicAdd(&stat[256 + o], q); }
    }
}

// ---------------- TC layer: y = W @ relu(bn(x)); split-bf16 MMA; fused stats ----------------
template <int CIN, int COUT>
__global__ void __launch_bounds__(256) k_layer_tc(
    const float* __restrict__ x, const float* __restrict__ W,
    const float* __restrict__ stat_in,
    const float* __restrict__ gam, const float* __restrict__ bet,
    float* __restrict__ y, float* __restrict__ stat_out) {
    const int b = blockIdx.y;
    const int n0 = blockIdx.x * 128;
    const int o0 = blockIdx.z * 64;
    __shared__ float scale[CIN], shift[CIN];
    __shared__ __nv_bfloat16 sAh[64][16], sAl[64][16];
    __shared__ __nv_bfloat16 sBh[16][128], sBl[16][128];
    int t = threadIdx.x, lane = t & 31, warp = t >> 5;
    int wm = warp >> 2, wn = warp & 3;
    if (t < CIN) {
        float inv = 1.f / (NB * (float)NPTS);
        float mu = stat_in[t] * inv;
        float var = stat_in[256 + t] * inv - mu * mu;
        float sc = gam[t] * rsqrtf(var + BN_EPS);
        scale[t] = sc;
        shift[t] = bet[t] - mu * sc;
    }
    __syncthreads();

    float acc[2][4][4];
#pragma unroll
    for (int i = 0; i < 2; i++)
#pragma unroll
        for (int j = 0; j < 4; j++)
#pragma unroll
            for (int k = 0; k < 4; k++) acc[i][j][k] = 0.f;

    const int kk = t >> 4;
    const int nn = (t & 15) * 8;
    const bool fast = (n0 + 128 <= NPTS);
    const int wo = t >> 2;
    const int wk = (t & 3) * 4;

    for (int c0 = 0; c0 < CIN; c0 += 16) {
        {
            int c = c0 + kk;
            const float* src = x + ((size_t)b * CIN + c) * NPTS + n0 + nn;
            float sc = scale[c], sh = shift[c];
            float vv[8];
            bool vd[8];
            if (fast) {
                float4 a0 = *(const float4*)src;
                float4 a1 = *(const float4*)(src + 4);
                vv[0] = a0.x; vv[1] = a0.y; vv[2] = a0.z; vv[3] = a0.w;
                vv[4] = a1.x; vv[5] = a1.y; vv[6] = a1.z; vv[7] = a1.w;
#pragma unroll
                for (int j = 0; j < 8; ++j) vd[j] = true;
            } else {
#pragma unroll
                for (int j = 0; j < 8; ++j) {
                    vd[j] = (n0 + nn + j < NPTS);
                    vv[j] = vd[j] ? src[j] : 0.f;
                }
            }
#pragma unroll
            for (int j = 0; j < 8; ++j) {
                float f = vd[j] ? fmaxf(fmaf(vv[j], sc, sh), 0.f) : 0.f;
                __nv_bfloat16 h = __float2bfloat16(f);
                sBh[kk][nn + j] = h;
                sBl[kk][nn + j] = __float2bfloat16(f - __bfloat162float(h));
            }
        }
        {
            float4 wv = *(const float4*)&W[(size_t)(o0 + wo) * CIN + c0 + wk];
            float ww[4] = {wv.x, wv.y, wv.z, wv.w};
#pragma unroll
            for (int j = 0; j < 4; ++j) {
                __nv_bfloat16 h = __float2bfloat16(ww[j]);
                sAh[wo][wk + j] = h;
                sAl[wo][wk + j] = __float2bfloat16(ww[j] - __bfloat162float(h));
            }
        }
        __syncthreads();

        unsigned ah[2][4], al[2][4], bh[8], bl[8];
#pragma unroll
        for (int mf = 0; mf < 2; ++mf) {
            int row = wm * 32 + mf * 16 + (lane & 15);
            int colk = (lane >> 4) * 8;
            unsigned p1 = (unsigned)__cvta_generic_to_shared(&sAh[row][colk]);
            LDSM_X4(ah[mf], p1);
            unsigned p2 = (unsigned)__cvta_generic_to_shared(&sAl[row][colk]);
            LDSM_X4(al[mf], p2);
        }
        {
            int coln = wn * 32 + (lane >> 4) * 8;
            unsigned p1 = (unsigned)__cvta_generic_to_shared(&sBh[lane & 15][coln]);
            LDSM_X4_T(bh, p1);
            unsigned p2 = (unsigned)__cvta_generic_to_shared(&sBh[lane & 15][coln + 16]);
            LDSM_X4_T(bh + 4, p2);
            unsigned p3 = (unsigned)__cvta_generic_to_shared(&sBl[lane & 15][coln]);
            LDSM_X4_T(bl, p3);
            unsigned p4 = (unsigned)__cvta_generic_to_shared(&sBl[lane & 15][coln + 16]);
            LDSM_X4_T(bl + 4, p4);
        }
#pragma unroll
        for (int mf = 0; mf < 2; ++mf)
#pragma unroll
            for (int ng = 0; ng < 4; ++ng) {
                MMA_BF16(acc[mf][ng], ah[mf], &bh[ng * 2]);
                MMA_BF16(acc[mf][ng], ah[mf], &bl[ng * 2]);
                MMA_BF16(acc[mf][ng], al[mf], &bh[ng * 2]);
            }
        __syncthreads();
    }

#pragma unroll
    for (int mf = 0; mf < 2; ++mf)
#pragma unroll
        for (int h = 0; h < 2; ++h) {
            int rg = o0 + wm * 32 + mf * 16 + (lane >> 2) + h * 8;
            float s = 0.f, q = 0.f;
#pragma unroll
            for (int ng = 0; ng < 4; ++ng) {
                int cg = n0 + wn * 32 + ng * 8 + (lane & 3) * 2;
                float v0 = acc[mf][ng][h * 2 + 0];
                float v1 = acc[mf][ng][h * 2 + 1];
                if (cg < NPTS) {
                    float* yp = y + ((size_t)b * COUT + rg) * NPTS + cg;
                    yp[0] = v0;
                    yp[1] = v1;
                }
                s += v0 + v1;
                q += v0 * v0 + v1 * v1;
            }
            s += __shfl_xor_sync(0xffffffffu, s, 1);
            q += __shfl_xor_sync(0xffffffffu, q, 1);
            s += __shfl_xor_sync(0xffffffffu, s, 2);
            q += __shfl_xor_sync(0xffffffffu, q, 2);
            if ((lane & 3) == 0) {
                atomicAdd(&stat_out[rg], s);
                atomicAdd(&stat_out[256 + rg], q);
            }
        }
}

// ---------------- TC SYRK (R10/R13-validated) ----------------
__global__ void __launch_bounds__(256) k_syrk(
    const float* __restrict__ y5, const float* __restrict__ stat_in,
    const float* __restrict__ gam, const float* __restrict__ bet,
    float* __restrict__ Sp, float* __restrict__ r) {
    const int b = blockIdx.y, ks = blockIdx.z;
    int ti, tj;
    if (blockIdx.x == 0)      { ti = 0; tj = 0; }
    else if (blockIdx.x == 1) { ti = 0; tj = 1; }
    else                      { ti = 1; tj = 1; }
    const int i0 = ti * 128, j0 = tj * 128;
    const int nstart = ks * 2000;
    __shared__ float scale[256], shift[256];
    __shared__ __nv_bfloat16 sAh[128][16], sAl[128][16];
    __shared__ __nv_bfloat16 sBh[16][128], sBl[16][128];
    int t = threadIdx.x, lane = t & 31, warp = t >> 5;
    int wm = warp >> 2, wn = warp & 3;
    {
        float inv = 1.f / (NB * (float)NPTS);
        float mu = stat_in[t] * inv;
        float var = stat_in[256 + t] * inv - mu * mu;
        float sc = gam[t] * rsqrtf(var + BN_EPS);
        scale[t] = sc;
        shift[t] = bet[t] - mu * sc;
    }
    __syncthreads();
    float acc[4][4][4];
#pragma unroll
    for (int i = 0; i < 4; i++)
#pragma unroll
        for (int j = 0; j < 4; j++)
#pragma unroll
            for (int k = 0; k < 4; k++) acc[i][j][k] = 0.f;
    const bool diag = (ti == tj);
    float rsum = 0.f;
    const int ca = t >> 1;
    const int kh = (t & 1) * 8;

    for (int n0 = nstart; n0 < nstart + 2000; n0 += 16) {
        {
            const float* src = y5 + ((size_t)b * 256 + i0 + ca) * NPTS + n0 + kh;
            float4 v0 = *(const float4*)src;
            float4 v1 = *(const float4*)(src + 4);
            float vv[8] = {v0.x, v0.y, v0.z, v0.w, v1.x, v1.y, v1.z, v1.w};
            float sc = scale[i0 + ca], sh = shift[i0 + ca];
#pragma unroll
            for (int j = 0; j < 8; ++j) {
                float f = fmaxf(fmaf(vv[j], sc, sh), 0.f);
                if (diag) rsum += f;
                __nv_bfloat16 h = __float2bfloat16(f);
                sAh[ca][kh + j] = h;
                sAl[ca][kh + j] = __float2bfloat16(f - __bfloat162float(h));
            }
        }
        {
            const float* src = y5 + ((size_t)b * 256 + j0 + ca) * NPTS + n0 + kh;
            float4 v0 = *(const float4*)src;
            float4 v1 = *(const float4*)(src + 4);
            float vv[8] = {v0.x, v0.y, v0.z, v0.w, v1.x, v1.y, v1.z, v1.w};
            float sc = scale[j0 + ca], sh = shift[j0 + ca];
#pragma unroll
            for (int j = 0; j < 8; ++j) {
                float f = fmaxf(fmaf(vv[j], sc, sh), 0.f);
                __nv_bfloat16 h = __float2bfloat16(f);
                sBh[kh + j][ca] = h;
                sBl[kh + j][ca] = __float2bfloat16(f - __bfloat162float(h));
            }
        }
        __syncthreads();

        unsigned ah[4][4], al[4][4], bh[8], bl[8];
#pragma unroll
        for (int mf = 0; mf < 4; ++mf) {
            int row = wm * 64 + mf * 16 + (lane & 15);
            int colk = (lane >> 4) * 8;
            unsigned p1 = (unsigned)__cvta_generic_to_shared(&sAh[row][colk]);
            LDSM_X4(ah[mf], p1);
            unsigned p2 = (unsigned)__cvta_generic_to_shared(&sAl[row][colk]);
            LDSM_X4(al[mf], p2);
        }
        {
            int coln = wn * 32 + (lane >> 4) * 8;
            unsigned p1 = (unsigned)__cvta_generic_to_shared(&sBh[lane & 15][coln]);
            LDSM_X4_T(bh, p1);
            unsigned p2 = (unsigned)__cvta_generic_to_shared(&sBh[lane & 15][coln + 16]);
            LDSM_X4_T(bh + 4, p2);
            unsigned p3 = (unsigned)__cvta_generic_to_shared(&sBl[lane & 15][coln]);
            LDSM_X4_T(bl, p3);
            unsigned p4 = (unsigned)__cvta_generic_to_shared(&sBl[lane & 15][coln + 16]);
            LDSM_X4_T(bl + 4, p4);
        }
#pragma unroll
        for (int mf = 0; mf < 4; ++mf)
#pragma unroll
            for (int ng = 0; ng < 4; ++ng) {
                MMA_BF16(acc[mf][ng], ah[mf], &bh[ng * 2]);
                MMA_BF16(acc[mf][ng], ah[mf], &bl[ng * 2]);
                MMA_BF16(acc[mf][ng], al[mf], &bh[ng * 2]);
            }
        __syncthreads();
    }

    if (diag) {
        rsum += __shfl_xor_sync(0xffffffffu, rsum, 1);
        if ((t & 1) == 0) atomicAdd(&r[b * 256 + i0 + ca], rsum);
    }

    float* Sb = Sp + ((size_t)ks * NB + b) * 65536;
#pragma unroll
    for (int mf = 0; mf < 4; ++mf)
#pragma unroll
        for (int ng = 0; ng < 4; ++ng)
#pragma unroll
            for (int h = 0; h < 2; ++h) {
                int rg = i0 + wm * 64 + mf * 16 + (lane >> 2) + h * 8;
                int cg = j0 + wn * 32 + ng * 8 + (lane & 3) * 2;
                float v0 = acc[mf][ng][h * 2 + 0];
                float v1 = acc[mf][ng][h * 2 + 1];
                Sb[(size_t)rg * 256 + cg] = v0;
                Sb[(size_t)rg * 256 + cg + 1] = v1;
                if (!diag) {
                    Sb[(size_t)cg * 256 + rg] = v0;
                    Sb[(size_t)(cg + 1) * 256 + rg] = v1;
                }
            }
}

// ---------------- cov assembly + Frobenius norm + split-bf16 NS init (R6-validated) ----------------
__global__ void k_cov(const float* __restrict__ Sp, const float* __restrict__ r,
                      float* __restrict__ covf,
                      __nv_bfloat16* __restrict__ Yh, __nv_bfloat16* __restrict__ Yl,
                      __nv_bfloat16* __restrict__ Zh, __nv_bfloat16* __restrict__ Zl,
                      float* __restrict__ nrm) {
    int b = blockIdx.x, t = threadIdx.x;
    const float invN = 1.f / (float)NPTS;
    __shared__ float ms[256], rbm[256];
    {
        float s = 0.f;
        for (int bb = 0; bb < NB; ++bb) s += r[bb * 256 + t];
        ms[t] = s / (NB * (float)NPTS);
        rbm[t] = r[b * 256 + t] * invN;
    }
    __syncthreads();
    float* Cb = covf + (size_t)b * 65536;
    __nv_bfloat16* Yhb = Yh + (size_t)b * 65536;
    __nv_bfloat16* Ylb = Yl + (size_t)b * 65536;
    __nv_bfloat16* Zhb = Zh + (size_t)b * 65536;
    __nv_bfloat16* Zlb = Zl + (size_t)b * 65536;
    float ssq = 0.f;
    for (int e = t; e < 65536; e += 256) {
        int i = e >> 8, j = e & 255;
        float s = 0.f;
        for (int ks = 0; ks < KSPLIT; ++ks) s += Sp[((size_t)ks * NB + b) * 65536 + e];
        float c = s * invN - rbm[i] * ms[j] - ms[i] * rbm[j] + ms[i] * ms[j];
        Cb[e] = c;
        ssq += c * c;
        Zhb[e] = __float2bfloat16((i == j) ? 1.f : 0.f);
        Zlb[e] = __float2bfloat16(0.f);
    }
    __shared__ float red[256];
    __shared__ float snorm;
    red[t] = ssq; __syncthreads();
    for (int st = 128; st > 0; st >>= 1) {
        if (t < st) red[t] += red[t + st];
        __syncthreads();
    }
    if (t == 0) { snorm = sqrtf(red[0]); nrm[b] = snorm; }
    __syncthreads();
    float inv = 1.f / snorm;
    for (int e = t; e < 65536; e += 256) {
        float v = Cb[e] * inv;
        __nv_bfloat16 h = __float2bfloat16(v);
        Yhb[e] = h;
        Ylb[e] = __float2bfloat16(v - __bfloat162float(h));
    }
}

// ---------------- NS tile: one 64x64 tile of C = A@B (256^2), split-bf16 (R6-validated) ----------------
__device__ __forceinline__ void ns_tile(
    const __nv_bfloat16* __restrict__ Ah, const __nv_bfloat16* __restrict__ Al,
    const __nv_bfloat16* __restrict__ Bh, const __nv_bfloat16* __restrict__ Bl,
    __nv_bfloat16* __restrict__ Ch, __nv_bfloat16* __restrict__ Cl,
    int i0, int j0, float alpha, int epi,
    __nv_bfloat16 (*sAh)[16], __nv_bfloat16 (*sAl)[16],
    __nv_bfloat16 (*sBh)[64], __nv_bfloat16 (*sBl)[64],
    int t, int lane, int wm, int wn) {
    float acc[2][2][4];
#pragma unroll
    for (int i = 0; i < 2; i++)
#pragma unroll
        for (int j = 0; j < 2; j++)
#pragma unroll
            for (int k = 0; k < 4; k++) acc[i][j][k] = 0.f;

    const int ra = t >> 2, ca = (t & 3) * 4;
    const int rb = t >> 4, cb = (t & 15) * 4;
    for (int k0 = 0; k0 < 256; k0 += 16) {
        *(uint2*)&sAh[ra][ca] = *(const uint2*)&Ah[(size_t)(i0 + ra) * 256 + k0 + ca];
        *(uint2*)&sAl[ra][ca] = *(const uint2*)&Al[(size_t)(i0 + ra) * 256 + k0 + ca];
        *(uint2*)&sBh[rb][cb] = *(const uint2*)&Bh[(size_t)(k0 + rb) * 256 + j0 + cb];
        *(uint2*)&sBl[rb][cb] = *(const uint2*)&Bl[(size_t)(k0 + rb) * 256 + j0 + cb];
        __syncthreads();

        unsigned ah[2][4], al[2][4], bh[4], bl[4];
#pragma unroll
        for (int mf = 0; mf < 2; ++mf) {
            int row = wm * 32 + mf * 16 + (lane & 15);
            int col = (lane >> 4) * 8;
            unsigned a1 = (unsigned)__cvta_generic_to_shared(&sAh[row][col]);
            LDSM_X4(ah[mf], a1);
            unsigned a2 = (unsigned)__cvta_generic_to_shared(&sAl[row][col]);
            LDSM_X4(al[mf], a2);
        }
        {
            int col = wn * 16 + (lane >> 4) * 8;
            unsigned a1 = (unsigned)__cvta_generic_to_shared(&sBh[lane & 15][col]);
            LDSM_X4_T(bh, a1);
            unsigned a2 = (unsigned)__cvta_generic_to_shared(&sBl[lane & 15][col]);
            LDSM_X4_T(bl, a2);
        }
#pragma unroll
        for (int mf = 0; mf < 2; ++mf)
#pragma unroll
            for (int nf = 0; nf < 2; ++nf) {
                MMA_BF16(acc[mf][nf], ah[mf], &bh[nf * 2]);
                MMA_BF16(acc[mf][nf], ah[mf], &bl[nf * 2]);
                MMA_BF16(acc[mf][nf], al[mf], &bh[nf * 2]);
            }
        __syncthreads();
    }

    const float am1 = alpha - 1.f;
#pragma unroll
    for (int mf = 0; mf < 2; ++mf)
#pragma unroll
        for (int nf = 0; nf < 2; ++nf)
#pragma unroll
            for (int h = 0; h < 2; ++h) {
                int rg = i0 + wm * 32 + mf * 16 + (lane >> 2) + h * 8;
                int cg = j0 + wn * 16 + nf * 8 + (lane & 3) * 2;
                float v0 = acc[mf][nf][h * 2 + 0];
                float v1 = acc[mf][nf][h * 2 + 1];
                if (epi) {
                    v0 = ((rg == cg) ? alpha : 0.f) - am1 * v0;
                    v1 = ((rg == cg + 1) ? alpha : 0.f) - am1 * v1;
                }
                __nv_bfloat16 h0 = __float2bfloat16(v0);
                __nv_bfloat16 h1 = __float2bfloat16(v1);
                __nv_bfloat16 l0 = __float2bfloat16(v0 - __bfloat162float(h0));
                __nv_bfloat16 l1 = __float2bfloat16(v1 - __bfloat162float(h1));
                __nv_bfloat162 hp; hp.x = h0; hp.y = h1;
                __nv_bfloat162 lp; lp.x = l0; lp.y = l1;
                *(__nv_bfloat162*)&Ch[(size_t)rg * 256 + cg] = hp;
                *(__nv_bfloat162*)&Cl[(size_t)rg * 256 + cg] = lp;
            }
}

// ---------------- fast sense-reversing grid barrier (volatile-poll, no atomic spin) ----------------
__device__ __forceinline__ void gridbar(unsigned* sense_local) {
    __syncthreads();
    if (threadIdx.x == 0) {
        unsigned s = *sense_local ^ 1u;
        __threadfence();                                   // release
        unsigned old = atomicAdd(&g_bar2[0], 1u);
        if (old == NS_GRID - 1) {
            atomicExch(&g_bar2[0], 0u);                    // reset count
            __threadfence();
            atomicExch(&g_bar2[1], s);                     // flip sense
        } else {
            volatile unsigned* vs = (volatile unsigned*)&g_bar2[1];
            while (*vs != s) __nanosleep(64);
        }
        __threadfence();                                   // acquire
        *sense_local = s;
    }
    __syncthreads();
}

// ---------------- persistent coupled Newton-Schulz (22 iterations, 1 launch) ----------------
__global__ void __launch_bounds__(256, 2)
k_nsper(__nv_bfloat16* Yh, __nv_bfloat16* Yl,
        __nv_bfloat16* Zh, __nv_bfloat16* Zl,
        __nv_bfloat16* Ph, __nv_bfloat16* Pl,
        __nv_bfloat16* Y2h, __nv_bfloat16* Y2l,
        __nv_bfloat16* Z2h, __nv_bfloat16* Z2l) {
    __shared__ __nv_bfloat16 sAh[64][16], sAl[64][16];
    __shared__ __nv_bfloat16 sBh[16][64], sBl[16][64];
    int t = threadIdx.x, lane = t & 31, warp = t >> 5;
    int wm = warp >> 2, wn = warp & 3;
    unsigned sense = 0;
    __nv_bfloat16 *cYh = Yh, *cYl = Yl, *cZh = Zh, *cZl = Zl;
    __nv_bfloat16 *nYh = Y2h, *nYl = Y2l, *nZh = Z2h, *nZl = Z2l;

    for (int it = 0; it < 22; ++it) {
        float alpha = (it < 16) ? 1.9f : 1.5f;
        // phase 1: P = alpha*I - (alpha-1) * Z @ Y   (256 tile jobs, 1 per CTA)
        {
            int job = blockIdx.x;
            int b = job >> 4, tile = job & 15;
            int i0 = (tile >> 2) * 64, j0 = (tile & 3) * 64;
            size_t o = (size_t)b * 65536;
            ns_tile(cZh + o, cZl + o, cYh + o, cYl + o, Ph + o, Pl + o,
                    i0, j0, alpha, 1, sAh, sAl, sBh, sBl, t, lane, wm, wn);
        }
        gridbar(&sense);
        // phase 2: Y' = Y @ P (jobs 0..255), Z' = P @ Z (jobs 256..511)
        for (int job = blockIdx.x; job < 512; job += NS_GRID) {
            int b = (job >> 4) & 15, tile = job & 15;
            int i0 = (tile >> 2) * 64, j0 = (tile & 3) * 64;
            size_t o = (size_t)b * 65536;
            if (job < 256)
                ns_tile(cYh + o, cYl + o, Ph + o, Pl + o, nYh + o, nYl + o,
                        i0, j0, 0.f, 0, sAh, sAl, sBh, sBl, t, lane, wm, wn);
            else
                ns_tile(Ph + o, Pl + o, cZh + o, cZl + o, nZh + o, nZl + o,
                        i0, j0, 0.f, 0, sAh, sAl, sBh, sBl, t, lane, wm, wn);
        }
        gridbar(&sense);
        __nv_bfloat16* s;
        s = cYh; cYh = nYh; nYh = s;  s = cYl; cYl = nYl; nYl = s;
        s = cZh; cZh = nZh; nZh = s;  s = cZl; cZl = nZl; nZl = s;
    }
    // 22 (even) swaps: final Y is back in Yh/Yl
}

// ---------------- FC partials over 4096-k chunks (reads split Y; R6-validated) ----------------
__global__ void k_fc(const __nv_bfloat16* __restrict__ Yh,
                     const __nv_bfloat16* __restrict__ Yl,
                     const float* __restrict__ nrm,
                     const float* __restrict__ Wfc, float* __restrict__ part) {
    int o0 = blockIdx.x * 16, k0 = blockIdx.y * 4096;
    __shared__ float vs[16][129];
    __shared__ float wsm[16][129];
    __shared__ float sq[16];
    int t = threadIdx.x;
    if (t < 16) sq[t] = sqrtf(nrm[t]);
    __syncthreads();
    int oo = t & 15, bb = t >> 4;
    float acc = 0.f;
    for (int kc = 0; kc < 4096; kc += 128) {
#pragma unroll
        for (int i = 0; i < 8; ++i) {
            int e = t + i * 256; int row = e >> 7, kk = e & 127;
            size_t idx = (size_t)row * 65536 + k0 + kc + kk;
            vs[row][kk] = sq[row] * (__bfloat162float(Yh[idx]) + __bfloat162float(Yl[idx]));
            wsm[row][kk] = Wfc[(size_t)(o0 + row) * 65536 + k0 + kc + kk];
        }
        __syncthreads();
#pragma unroll
        for (int kk = 0; kk < 128; kk++) acc = fmaf(wsm[oo][kk], vs[bb][kk], acc);
        __syncthreads();
    }
    part[((size_t)blockIdx.y * 256 + o0 + oo) * 16 + bb] = acc;
}

// ---------------- finalize: bias + L2 normalize ----------------
__global__ void k_fin(const float* __restrict__ part, const float* __restrict__ bfc,
                      float* __restrict__ out) {
    int b = blockIdx.x, t = threadIdx.x;
    float v = bfc[t];
    for (int ks = 0; ks < 16; ++ks) v += part[((size_t)ks * 256 + t) * 16 + b];
    __shared__ float red[256];
    red[t] = v * v; __syncthreads();
    for (int st = 128; st > 0; st >>= 1) {
        if (t < st) red[t] += red[t + st];
        __syncthreads();
    }
    float nrm = fmaxf(sqrtf(red[0]), 1e-12f);
    out[b * 256 + t] = v / nrm;
}

// ---------------- host driver ----------------
static float* symaddr(const void* sym) {
    void* p = nullptr;
    cudaGetSymbolAddress(&p, sym);
    return (float*)p;
}
static __nv_bfloat16* symaddr_bf(const void* sym) {
    void* p = nullptr;
    cudaGetSymbolAddress(&p, sym);
    return (__nv_bfloat16*)p;
}

extern "C" void kernel_launch(void* const* d_in, const int* in_sizes, int n_in,
                              void* d_out, int out_size) {
    const float* pts = (const float*)d_in[0];
    const float* W[5]; const float* G[5]; const float* Bt[5];
    for (int l = 0; l < 5; ++l) {
        W[l]  = (const float*)d_in[1 + 3 * l];
        G[l]  = (const float*)d_in[2 + 3 * l];
        Bt[l] = (const float*)d_in[3 + 3 * l];
    }
    const float* Wfc = (const float*)d_in[16];
    const float* bfc = (const float*)d_in[17];
    float* out = (float*)d_out;

    float* bufA = symaddr(g_bufA);
    float* bufB = symaddr(g_bufB);
    float* y5   = symaddr(g_y5);
    float* stat = symaddr(g_stat);
    float* r    = symaddr(g_r);
    float* Sp   = symaddr(g_Spart);
    float* nrm  = symaddr(g_nrm);
    float* covf = symaddr(g_cov);
    float* part = symaddr(g_part);
    void* barp = nullptr; cudaGetSymbolAddress(&barp, g_bar2);
    __nv_bfloat16* Yh  = symaddr_bf(g_Yh);
    __nv_bfloat16* Yl  = symaddr_bf(g_Yl);
    __nv_bfloat16* Zh  = symaddr_bf(g_Zh);
    __nv_bfloat16* Zl  = symaddr_bf(g_Zl);
    __nv_bfloat16* Ph  = symaddr_bf(g_Ph);
    __nv_bfloat16* Pl  = symaddr_bf(g_Pl);
    __nv_bfloat16* Y2h = symaddr_bf(g_Y2h);
    __nv_bfloat16* Y2l = symaddr_bf(g_Y2l);
    __nv_bfloat16* Z2h = symaddr_bf(g_Z2h);
    __nv_bfloat16* Z2l = symaddr_bf(g_Z2l);

    const int NT = (NPTS + 127) / 128;  // 79

    cudaMemsetAsync(stat, 0, 5 * 512 * sizeof(float), 0);
    cudaMemsetAsync(r, 0, NB * 256 * sizeof(float), 0);
    cudaMemsetAsync(barp, 0, 2 * sizeof(unsigned), 0);

    // MLP 3->64->64->64->128->256 on tensor cores; BN finalize in prologues
    k_layer0<<<dim3((NPTS + 255) / 256, NB), 256>>>(pts, W[0], bufA, stat + 0 * 512);
    k_layer_tc<64, 64><<<dim3(NT, NB, 1), 256>>>(bufA, W[1], stat + 0 * 512, G[0], Bt[0],
                                                 bufB, stat + 1 * 512);
    k_layer_tc<64, 64><<<dim3(NT, NB, 1), 256>>>(bufB, W[2], stat + 1 * 512, G[1], Bt[1],
                                                 bufA, stat + 2 * 512);
    k_layer_tc<64, 128><<<dim3(NT, NB, 2), 256>>>(bufA, W[3], stat + 2 * 512, G[2], Bt[2],
                                                  bufB, stat + 3 * 512);
    k_layer_tc<128, 256><<<dim3(NT, NB, 4), 256>>>(bufB, W[4], stat + 3 * 512, G[3], Bt[3],
                                                   y5, stat + 4 * 512);

    // second-order pooling on tensor cores
    k_syrk<<<dim3(3, NB, KSPLIT), 256>>>(y5, stat + 4 * 512, G[4], Bt[4], Sp, r);
    k_cov<<<NB, 256>>>(Sp, r, covf, Yh, Yl, Zh, Zl, nrm);

    // persistent coupled Newton-Schulz on tensor cores (single launch, fast barrier)
    k_nsper<<<NS_GRID, 256>>>(Yh, Yl, Zh, Zl, Ph, Pl, Y2h, Y2l, Z2h, Z2l);

    // FC + L2 normalize
    k_fc<<<dim3(16, 16), 256>>>(Yh, Yl, nrm, Wfc, part);
    k_fin<<<NB, 256>>>(part, bfc, out);
}

// round 17
// speedup vs baseline: 1.1270x; 1.1270x over previous
#include <cuda_runtime.h>
#include <cuda_bf16.h>
#include <cstddef>

#define NPTS 10000
#define NB 16
#define BN_EPS 1e-5f
#define KSPLIT 5

// ---------------- static device scratch (allocation-free) ----------------
__device__ float g_bufA[NB * 64 * NPTS];
__device__ float g_bufB[NB * 128 * NPTS];
__device__ float g_y5[NB * 256 * NPTS];
__device__ float g_stat[5 * 512];
__device__ float g_r[NB * 256];
__device__ float g_Spart[KSPLIT * NB * 256 * 256];
__device__ float g_nrm[NB];
__device__ float g_Y[NB * 256 * 256];
__device__ float g_Z[NB * 256 * 256];
__device__ float g_P[NB * 256 * 256];
__device__ float g_Y2[NB * 256 * 256];
__device__ float g_Z2[NB * 256 * 256];
__device__ float g_part[16 * 256 * NB];

// ---------------- tensor-core fragment primitives (validated R6/R10/R13) ----------------
#define LDSM_X4(R, addr)                                                         \
    asm volatile("ldmatrix.sync.aligned.m8n8.x4.shared.b16 {%0,%1,%2,%3}, [%4];" \
                 : "=r"((R)[0]), "=r"((R)[1]), "=r"((R)[2]), "=r"((R)[3])        \
                 : "r"(addr))
#define LDSM_X4_T(R, addr)                                                             \
    asm volatile("ldmatrix.sync.aligned.m8n8.x4.trans.shared.b16 {%0,%1,%2,%3}, [%4];" \
                 : "=r"((R)[0]), "=r"((R)[1]), "=r"((R)[2]), "=r"((R)[3])              \
                 : "r"(addr))
#define MMA_BF16(C, A, B)                                                          \
    asm volatile(                                                                  \
        "mma.sync.aligned.m16n8k16.row.col.f32.bf16.bf16.f32 "                     \
        "{%0,%1,%2,%3},{%4,%5,%6,%7},{%8,%9},{%0,%1,%2,%3};"                       \
        : "+f"((C)[0]), "+f"((C)[1]), "+f"((C)[2]), "+f"((C)[3])                   \
        : "r"((A)[0]), "r"((A)[1]), "r"((A)[2]), "r"((A)[3]), "r"((B)[0]),         \
          "r"((B)[1]))

union Pack8 { uint4 u; __nv_bfloat16 b[8]; };
union Pack4 { uint2 u; __nv_bfloat16 b[4]; };

// ---------------- layer 0: 3 -> 64 raw, fused BN-stat accumulation ----------------
__global__ void k_layer0(const float* __restrict__ pts, const float* __restrict__ W0,
                         float* __restrict__ y, float* __restrict__ stat) {
    __shared__ float w[192];
    int t = threadIdx.x;
    if (t < 192) w[t] = W0[t];
    __syncthreads();
    int b = blockIdx.y;
    int n = blockIdx.x * 256 + t;
    bool valid = (n < NPTS);
    float p0 = 0.f, p1 = 0.f, p2 = 0.f;
    if (valid) {
        const float* p = pts + ((size_t)b * NPTS + n) * 3;
        p0 = p[0]; p1 = p[1]; p2 = p[2];
    }
    float* yo = y + (size_t)b * 64 * NPTS + n;
    int lane = t & 31;
#pragma unroll
    for (int o = 0; o < 64; ++o) {
        float v = w[o * 3] * p0 + w[o * 3 + 1] * p1 + w[o * 3 + 2] * p2;
        if (valid) yo[(size_t)o * NPTS] = v;
        float s = v, q = v * v;
#pragma unroll
        for (int m2 = 16; m2 >= 1; m2 >>= 1) {
            s += __shfl_xor_sync(0xffffffffu, s, m2);
            q += __shfl_xor_sync(0xffffffffu, q, m2);
        }
        if (lane == 0) { atomicAdd(&stat[o], s); atomicAdd(&stat[256 + o], q); }
    }
}

// ---------------- TC layer: y = W @ relu(bn(x)); split-bf16 MMA; packed STS ----------------
template <int CIN, int COUT>
__global__ void __launch_bounds__(256) k_layer_tc(
    const float* __restrict__ x, const float* __restrict__ W,
    const float* __restrict__ stat_in,
    const float* __restrict__ gam, const float* __restrict__ bet,
    float* __restrict__ y, float* __restrict__ stat_out) {
    const int b = blockIdx.y;
    const int n0 = blockIdx.x * 128;
    const int o0 = blockIdx.z * 64;
    __shared__ float scale[CIN], shift[CIN];
    __shared__ __nv_bfloat16 sAh[64][16], sAl[64][16];
    __shared__ __nv_bfloat16 sBh[16][128], sBl[16][128];
    int t = threadIdx.x, lane = t & 31, warp = t >> 5;
    int wm = warp >> 2, wn = warp & 3;
    if (t < CIN) {
        float inv = 1.f / (NB * (float)NPTS);
        float mu = stat_in[t] * inv;
        float var = stat_in[256 + t] * inv - mu * mu;
        float sc = gam[t] * rsqrtf(var + BN_EPS);
        scale[t] = sc;
        shift[t] = bet[t] - mu * sc;
    }
    __syncthreads();

    float acc[2][4][4];
#pragma unroll
    for (int i = 0; i < 2; i++)
#pragma unroll
        for (int j = 0; j < 4; j++)
#pragma unroll
            for (int k = 0; k < 4; k++) acc[i][j][k] = 0.f;

    const int kk = t >> 4;
    const int nn = (t & 15) * 8;
    const bool fast = (n0 + 128 <= NPTS);
    const int wo = t >> 2;
    const int wk = (t & 3) * 4;

    for (int c0 = 0; c0 < CIN; c0 += 16) {
        // ---- activation tile B[k=16][n=128]: BN+ReLU+split, packed 16B stores ----
        {
            int c = c0 + kk;
            const float* src = x + ((size_t)b * CIN + c) * NPTS + n0 + nn;
            float sc = scale[c], sh = shift[c];
            float vv[8];
            bool vd[8];
            if (fast) {
                float4 a0 = *(const float4*)src;
                float4 a1 = *(const float4*)(src + 4);
                vv[0] = a0.x; vv[1] = a0.y; vv[2] = a0.z; vv[3] = a0.w;
                vv[4] = a1.x; vv[5] = a1.y; vv[6] = a1.z; vv[7] = a1.w;
#pragma unroll
                for (int j = 0; j < 8; ++j) vd[j] = true;
            } else {
#pragma unroll
                for (int j = 0; j < 8; ++j) {
                    vd[j] = (n0 + nn + j < NPTS);
                    vv[j] = vd[j] ? src[j] : 0.f;
                }
            }
            Pack8 uh, ul;
#pragma unroll
            for (int j = 0; j < 8; ++j) {
                float f = vd[j] ? fmaxf(fmaf(vv[j], sc, sh), 0.f) : 0.f;
                __nv_bfloat16 h = __float2bfloat16(f);
                uh.b[j] = h;
                ul.b[j] = __float2bfloat16(f - __bfloat162float(h));
            }
            *(uint4*)&sBh[kk][nn] = uh.u;
            *(uint4*)&sBl[kk][nn] = ul.u;
        }
        // ---- weight tile A[o=64][k=16]: split, packed 8B stores ----
        {
            float4 wv = *(const float4*)&W[(size_t)(o0 + wo) * CIN + c0 + wk];
            float ww[4] = {wv.x, wv.y, wv.z, wv.w};
            Pack4 vh, vl;
#pragma unroll
            for (int j = 0; j < 4; ++j) {
                __nv_bfloat16 h = __float2bfloat16(ww[j]);
                vh.b[j] = h;
                vl.b[j] = __float2bfloat16(ww[j] - __bfloat162float(h));
            }
            *(uint2*)&sAh[wo][wk] = vh.u;
            *(uint2*)&sAl[wo][wk] = vl.u;
        }
        __syncthreads();

        unsigned ah[2][4], al[2][4], bh[8], bl[8];
#pragma unroll
        for (int mf = 0; mf < 2; ++mf) {
            int row = wm * 32 + mf * 16 + (lane & 15);
            int colk = (lane >> 4) * 8;
            unsigned p1 = (unsigned)__cvta_generic_to_shared(&sAh[row][colk]);
            LDSM_X4(ah[mf], p1);
            unsigned p2 = (unsigned)__cvta_generic_to_shared(&sAl[row][colk]);
            LDSM_X4(al[mf], p2);
        }
        {
            int coln = wn * 32 + (lane >> 4) * 8;
            unsigned p1 = (unsigned)__cvta_generic_to_shared(&sBh[lane & 15][coln]);
            LDSM_X4_T(bh, p1);
            unsigned p2 = (unsigned)__cvta_generic_to_shared(&sBh[lane & 15][coln + 16]);
            LDSM_X4_T(bh + 4, p2);
            unsigned p3 = (unsigned)__cvta_generic_to_shared(&sBl[lane & 15][coln]);
            LDSM_X4_T(bl, p3);
            unsigned p4 = (unsigned)__cvta_generic_to_shared(&sBl[lane & 15][coln + 16]);
            LDSM_X4_T(bl + 4, p4);
        }
#pragma unroll
        for (int mf = 0; mf < 2; ++mf)
#pragma unroll
            for (int ng = 0; ng < 4; ++ng) {
                MMA_BF16(acc[mf][ng], ah[mf], &bh[ng * 2]);
                MMA_BF16(acc[mf][ng], ah[mf], &bl[ng * 2]);
                MMA_BF16(acc[mf][ng], al[mf], &bh[ng * 2]);
            }
        __syncthreads();
    }

    // ---- store y (fp32) + fused BN-stat epilogue ----
#pragma unroll
    for (int mf = 0; mf < 2; ++mf)
#pragma unroll
        for (int h = 0; h < 2; ++h) {
            int rg = o0 + wm * 32 + mf * 16 + (lane >> 2) + h * 8;
            float s = 0.f, q = 0.f;
#pragma unroll
            for (int ng = 0; ng < 4; ++ng) {
                int cg = n0 + wn * 32 + ng * 8 + (lane & 3) * 2;
                float v0 = acc[mf][ng][h * 2 + 0];
                float v1 = acc[mf][ng][h * 2 + 1];
                if (cg < NPTS) {
                    float* yp = y + ((size_t)b * COUT + rg) * NPTS + cg;
                    yp[0] = v0;
                    yp[1] = v1;
                }
                s += v0 + v1;
                q += v0 * v0 + v1 * v1;
            }
            s += __shfl_xor_sync(0xffffffffu, s, 1);
            q += __shfl_xor_sync(0xffffffffu, q, 1);
            s += __shfl_xor_sync(0xffffffffu, s, 2);
            q += __shfl_xor_sync(0xffffffffu, q, 2);
            if ((lane & 3) == 0) {
                atomicAdd(&stat_out[rg], s);
                atomicAdd(&stat_out[256 + rg], q);
            }
        }
}

// ---------------- TC SYRK (R10/R13-validated; packed A-tile stores) ----------------
__global__ void __launch_bounds__(256) k_syrk(
    const float* __restrict__ y5, const float* __restrict__ stat_in,
    const float* __restrict__ gam, const float* __restrict__ bet,
    float* __restrict__ Sp, float* __restrict__ r) {
    const int b = blockIdx.y, ks = blockIdx.z;
    int ti, tj;
    if (blockIdx.x == 0)      { ti = 0; tj = 0; }
    else if (blockIdx.x == 1) { ti = 0; tj = 1; }
    else                      { ti = 1; tj = 1; }
    const int i0 = ti * 128, j0 = tj * 128;
    const int nstart = ks * 2000;
    __shared__ float scale[256], shift[256];
    __shared__ __nv_bfloat16 sAh[128][16], sAl[128][16];
    __shared__ __nv_bfloat16 sBh[16][128], sBl[16][128];
    int t = threadIdx.x, lane = t & 31, warp = t >> 5;
    int wm = warp >> 2, wn = warp & 3;
    {
        float inv = 1.f / (NB * (float)NPTS);
        float mu = stat_in[t] * inv;
        float var = stat_in[256 + t] * inv - mu * mu;
        float sc = gam[t] * rsqrtf(var + BN_EPS);
        scale[t] = sc;
        shift[t] = bet[t] - mu * sc;
    }
    __syncthreads();
    float acc[4][4][4];
#pragma unroll
    for (int i = 0; i < 4; i++)
#pragma unroll
        for (int j = 0; j < 4; j++)
#pragma unroll
            for (int k = 0; k < 4; k++) acc[i][j][k] = 0.f;
    const bool diag = (ti == tj);
    float rsum = 0.f;
    const int ca = t >> 1;
    const int kh = (t & 1) * 8;

    for (int n0 = nstart; n0 < nstart + 2000; n0 += 16) {
        {
            const float* src = y5 + ((size_t)b * 256 + i0 + ca) * NPTS + n0 + kh;
            float4 v0 = *(const float4*)src;
            float4 v1 = *(const float4*)(src + 4);
            float vv[8] = {v0.x, v0.y, v0.z, v0.w, v1.x, v1.y, v1.z, v1.w};
            float sc = scale[i0 + ca], sh = shift[i0 + ca];
            Pack8 uh, ul;
#pragma unroll
            for (int j = 0; j < 8; ++j) {
                float f = fmaxf(fmaf(vv[j], sc, sh), 0.f);
                if (diag) rsum += f;
                __nv_bfloat16 h = __float2bfloat16(f);
                uh.b[j] = h;
                ul.b[j] = __float2bfloat16(f - __bfloat162float(h));
            }
            *(uint4*)&sAh[ca][kh] = uh.u;
            *(uint4*)&sAl[ca][kh] = ul.u;
        }
        {
            const float* src = y5 + ((size_t)b * 256 + j0 + ca) * NPTS + n0 + kh;
            float4 v0 = *(const float4*)src;
            float4 v1 = *(const float4*)(src + 4);
            float vv[8] = {v0.x, v0.y, v0.z, v0.w, v1.x, v1.y, v1.z, v1.w};
            float sc = scale[j0 + ca], sh = shift[j0 + ca];
#pragma unroll
            for (int j = 0; j < 8; ++j) {
                float f = fmaxf(fmaf(vv[j], sc, sh), 0.f);
                __nv_bfloat16 h = __float2bfloat16(f);
                sBh[kh + j][ca] = h;
                sBl[kh + j][ca] = __float2bfloat16(f - __bfloat162float(h));
            }
        }
        __syncthreads();

        unsigned ah[4][4], al[4][4], bh[8], bl[8];
#pragma unroll
        for (int mf = 0; mf < 4; ++mf) {
            int row = wm * 64 + mf * 16 + (lane & 15);
            int colk = (lane >> 4) * 8;
            unsigned p1 = (unsigned)__cvta_generic_to_shared(&sAh[row][colk]);
            LDSM_X4(ah[mf], p1);
            unsigned p2 = (unsigned)__cvta_generic_to_shared(&sAl[row][colk]);
            LDSM_X4(al[mf], p2);
        }
        {
            int coln = wn * 32 + (lane >> 4) * 8;
            unsigned p1 = (unsigned)__cvta_generic_to_shared(&sBh[lane & 15][coln]);
            LDSM_X4_T(bh, p1);
            unsigned p2 = (unsigned)__cvta_generic_to_shared(&sBh[lane & 15][coln + 16]);
            LDSM_X4_T(bh + 4, p2);
            unsigned p3 = (unsigned)__cvta_generic_to_shared(&sBl[lane & 15][coln]);
            LDSM_X4_T(bl, p3);
            unsigned p4 = (unsigned)__cvta_generic_to_shared(&sBl[lane & 15][coln + 16]);
            LDSM_X4_T(bl + 4, p4);
        }
#pragma unroll
        for (int mf = 0; mf < 4; ++mf)
#pragma unroll
            for (int ng = 0; ng < 4; ++ng) {
                MMA_BF16(acc[mf][ng], ah[mf], &bh[ng * 2]);
                MMA_BF16(acc[mf][ng], ah[mf], &bl[ng * 2]);
                MMA_BF16(acc[mf][ng], al[mf], &bh[ng * 2]);
            }
        __syncthreads();
    }

    if (diag) {
        rsum += __shfl_xor_sync(0xffffffffu, rsum, 1);
        if ((t & 1) == 0) atomicAdd(&r[b * 256 + i0 + ca], rsum);
    }

    float* Sb = Sp + ((size_t)ks * NB + b) * 65536;
#pragma unroll
    for (int mf = 0; mf < 4; ++mf)
#pragma unroll
        for (int ng = 0; ng < 4; ++ng)
#pragma unroll
            for (int h = 0; h < 2; ++h) {
                int rg = i0 + wm * 64 + mf * 16 + (lane >> 2) + h * 8;
                int cg = j0 + wn * 32 + ng * 8 + (lane & 3) * 2;
                float v0 = acc[mf][ng][h * 2 + 0];
                float v1 = acc[mf][ng][h * 2 + 1];
                Sb[(size_t)rg * 256 + cg] = v0;
                Sb[(size_t)rg * 256 + cg + 1] = v1;
                if (!diag) {
                    Sb[(size_t)cg * 256 + rg] = v0;
                    Sb[(size_t)(cg + 1) * 256 + rg] = v1;
                }
            }
}

// ---------------- cov assembly + Frobenius norm + NS init (fp32, R13) ----------------
__global__ void k_cov(const float* __restrict__ Sp, const float* __restrict__ r,
                      float* __restrict__ Y, float* __restrict__ Z,
                      float* __restrict__ nrm) {
    int b = blockIdx.x, t = threadIdx.x;
    const float invN = 1.f / (float)NPTS;
    __shared__ float ms[256], rbm[256];
    {
        float s = 0.f;
        for (int bb = 0; bb < NB; ++bb) s += r[bb * 256 + t];
        ms[t] = s / (NB * (float)NPTS);
        rbm[t] = r[b * 256 + t] * invN;
    }
    __syncthreads();
    float* Yb = Y + (size_t)b * 65536;
    float* Zb = Z + (size_t)b * 65536;
    float ssq = 0.f;
    for (int e = t; e < 65536; e += 256) {
        int i = e >> 8, j = e & 255;
        float s = 0.f;
        for (int ks = 0; ks < KSPLIT; ++ks) s += Sp[((size_t)ks * NB + b) * 65536 + e];
        float c = s * invN - rbm[i] * ms[j] - ms[i] * rbm[j] + ms[i] * ms[j];
        Yb[e] = c;
        ssq += c * c;
        Zb[e] = (i == j) ? 1.f : 0.f;
    }
    __shared__ float red[256];
    __shared__ float snorm;
    red[t] = ssq; __syncthreads();
    for (int st = 128; st > 0; st >>= 1) {
        if (t < st) red[t] += red[t + st];
        __syncthreads();
    }
    if (t == 0) { snorm = sqrtf(red[0]); nrm[b] = snorm; }
    __syncthreads();
    float inv = 1.f / snorm;
    for (int e = t; e < 65536; e += 256) Yb[e] *= inv;
}

// ---------------- batched 256^3 GEMM (tile 128x64), optional P-epilogue ----------------
__global__ void k_bgemm256(const float* __restrict__ A0, const float* __restrict__ B0,
                           float* __restrict__ C0, const float* __restrict__ A1,
                           const float* __restrict__ B1, float* __restrict__ C1,
                           float alpha, int epi) {
    const float* A = A0; const float* Bm = B0; float* C = C0;
    if (blockIdx.z == 1) { A = A1; Bm = B1; C = C1; }
    int b = blockIdx.y;
    A  += (size_t)b * 65536;
    Bm += (size_t)b * 65536;
    C  += (size_t)b * 65536;
    int i0 = (blockIdx.x >> 2) * 128, j0 = (blockIdx.x & 3) * 64;
    __shared__ float as[16][132];
    __shared__ float bsm[16][68];
    float acc[8][4];
#pragma unroll
    for (int i = 0; i < 8; i++)
#pragma unroll
        for (int j = 0; j < 4; j++) acc[i][j] = 0.f;
    int t = threadIdx.x, tx = t & 15, ty = t >> 4;
    for (int c0 = 0; c0 < 256; c0 += 16) {
#pragma unroll
        for (int i = 0; i < 8; ++i) {
            int e = t + i * 256; int ii = e >> 4, kk = e & 15;
            as[kk][ii] = A[(i0 + ii) * 256 + c0 + kk];
        }
#pragma unroll
        for (int i = 0; i < 4; ++i) {
            int e = t + i * 256; int kk = e >> 6, jj = e & 63;
            bsm[kk][jj] = Bm[(c0 + kk) * 256 + j0 + jj];
        }
        __syncthreads();
#pragma unroll
        for (int kk = 0; kk < 16; ++kk) {
            float4 a0 = *(const float4*)&as[kk][ty * 8];
            float4 a1 = *(const float4*)&as[kk][ty * 8 + 4];
            float4 bv = *(const float4*)&bsm[kk][tx * 4];
            float a[8] = {a0.x, a0.y, a0.z, a0.w, a1.x, a1.y, a1.z, a1.w};
            float bb[4] = {bv.x, bv.y, bv.z, bv.w};
#pragma unroll
            for (int i = 0; i < 8; i++)
#pragma unroll
                for (int j = 0; j < 4; j++) acc[i][j] = fmaf(a[i], bb[j], acc[i][j]);
        }
        __syncthreads();
    }
#pragma unroll
    for (int i = 0; i < 8; i++)
#pragma unroll
        for (int j = 0; j < 4; j++) {
            int ii = i0 + ty * 8 + i, jj = j0 + tx * 4 + j;
            float v = acc[i][j];
            if (epi) v = ((ii == jj) ? alpha : 0.f) - (alpha - 1.f) * v;
            C[ii * 256 + jj] = v;
        }
}

// ---------------- FC partials over 4096-k chunks ----------------
__global__ void k_fc(const float* __restrict__ Yfin, const float* __restrict__ nrm,
                     const float* __restrict__ Wfc, float* __restrict__ part) {
    int o0 = blockIdx.x * 16, k0 = blockIdx.y * 4096;
    __shared__ float vs[16][129];
    __shared__ float wsm[16][129];
    __shared__ float sq[16];
    int t = threadIdx.x;
    if (t < 16) sq[t] = sqrtf(nrm[t]);
    __syncthreads();
    int oo = t & 15, bb = t >> 4;
    float acc = 0.f;
    for (int kc = 0; kc < 4096; kc += 128) {
#pragma unroll
        for (int i = 0; i < 8; ++i) {
            int e = t + i * 256; int row = e >> 7, kk = e & 127;
            vs[row][kk]  = sq[row] * Yfin[(size_t)row * 65536 + k0 + kc + kk];
            wsm[row][kk] = Wfc[(size_t)(o0 + row) * 65536 + k0 + kc + kk];
        }
        __syncthreads();
#pragma unroll
        for (int kk = 0; kk < 128; kk++) acc = fmaf(wsm[oo][kk], vs[bb][kk], acc);
        __syncthreads();
    }
    part[((size_t)blockIdx.y * 256 + o0 + oo) * 16 + bb] = acc;
}

// ---------------- finalize: bias + L2 normalize ----------------
__global__ void k_fin(const float* __restrict__ part, const float* __restrict__ bfc,
                      float* __restrict__ out) {
    int b = blockIdx.x, t = threadIdx.x;
    float v = bfc[t];
    for (int ks = 0; ks < 16; ++ks) v += part[((size_t)ks * 256 + t) * 16 + b];
    __shared__ float red[256];
    red[t] = v * v; __syncthreads();
    for (int st = 128; st > 0; st >>= 1) {
        if (t < st) red[t] += red[t + st];
        __syncthreads();
    }
    float nrm = fmaxf(sqrtf(red[0]), 1e-12f);
    out[b * 256 + t] = v / nrm;
}

// ---------------- host driver ----------------
static float* symaddr(const void* sym) {
    void* p = nullptr;
    cudaGetSymbolAddress(&p, sym);
    return (float*)p;
}

extern "C" void kernel_launch(void* const* d_in, const int* in_sizes, int n_in,
                              void* d_out, int out_size) {
    const float* pts = (const float*)d_in[0];
    const float* W[5]; const float* G[5]; const float* Bt[5];
    for (int l = 0; l < 5; ++l) {
        W[l]  = (const float*)d_in[1 + 3 * l];
        G[l]  = (const float*)d_in[2 + 3 * l];
        Bt[l] = (const float*)d_in[3 + 3 * l];
    }
    const float* Wfc = (const float*)d_in[16];
    const float* bfc = (const float*)d_in[17];
    float* out = (float*)d_out;

    float* bufA = symaddr(g_bufA);
    float* bufB = symaddr(g_bufB);
    float* y5   = symaddr(g_y5);
    float* stat = symaddr(g_stat);
    float* r    = symaddr(g_r);
    float* Sp   = symaddr(g_Spart);
    float* nrm  = symaddr(g_nrm);
    float* Y    = symaddr(g_Y);
    float* Z    = symaddr(g_Z);
    float* P    = symaddr(g_P);
    float* Y2   = symaddr(g_Y2);
    float* Z2   = symaddr(g_Z2);
    float* part = symaddr(g_part);

    const int NT = (NPTS + 127) / 128;  // 79

    cudaMemsetAsync(stat, 0, 5 * 512 * sizeof(float), 0);
    cudaMemsetAsync(r, 0, NB * 256 * sizeof(float), 0);

    // MLP 3->64->64->64->128->256 on tensor cores; BN finalize in prologues
    k_layer0<<<dim3((NPTS + 255) / 256, NB), 256>>>(pts, W[0], bufA, stat + 0 * 512);
    k_layer_tc<64, 64><<<dim3(NT, NB, 1), 256>>>(bufA, W[1], stat + 0 * 512, G[0], Bt[0],
                                                 bufB, stat + 1 * 512);
    k_layer_tc<64, 64><<<dim3(NT, NB, 1), 256>>>(bufB, W[2], stat + 1 * 512, G[1], Bt[1],
                                                 bufA, stat + 2 * 512);
    k_layer_tc<64, 128><<<dim3(NT, NB, 2), 256>>>(bufA, W[3], stat + 2 * 512, G[2], Bt[2],
                                                  bufB, stat + 3 * 512);
    k_layer_tc<128, 256><<<dim3(NT, NB, 4), 256>>>(bufB, W[4], stat + 3 * 512, G[3], Bt[3],
                                                   y5, stat + 4 * 512);

    // second-order pooling on tensor cores
    k_syrk<<<dim3(3, NB, KSPLIT), 256>>>(y5, stat + 4 * 512, G[4], Bt[4], Sp, r);
    k_cov<<<NB, 256>>>(Sp, r, Y, Z, nrm);

    // coupled Newton-Schulz (fp32 launch chain — fastest measured variant)
    float* curY = Y; float* curZ = Z; float* nY = Y2; float* nZ = Z2;
    for (int it = 0; it < 22; ++it) {
        float alpha = (it < 16) ? 1.9f : 1.5f;
        k_bgemm256<<<dim3(8, NB, 1), 256>>>(curZ, curY, P, curZ, curY, P, alpha, 1);
        k_bgemm256<<<dim3(8, NB, 2), 256>>>(curY, P, nY, P, curZ, nZ, 0.f, 0);
        float* tY = curY; curY = nY; nY = tY;
        float* tZ = curZ; curZ = nZ; nZ = tZ;
    }

    // FC + L2 normalize
    k_fc<<<dim3(16, 16), 256>>>(curY, nrm, Wfc, part);
    k_fin<<<NB, 256>>>(part, bfc, out);
}